// round 1
// baseline (speedup 1.0000x reference)
#include <cuda_runtime.h>
#include <math.h>

#define T_SEQ 20
#define NF    812
#define HID   400
#define NG    1600            // 4*HID
#define BATCH 8192
#define MROWS (BATCH * T_SEQ) // 163840

// ---------------- device scratch (no runtime allocation allowed) ----------------
__device__ float g_G0[(size_t)MROWS * NG]; // 1.05 GB: precomputed input-side gates
__device__ float g_hA[BATCH * HID];
__device__ float g_hB[BATCH * HID];
__device__ float g_c [BATCH * HID];
__device__ float g_alpha[BATCH];
__device__ float g_wsum[HID];
__device__ float g_num[T_SEQ];
__device__ float g_den[T_SEQ];

// ---------------- init: zero recurrent state + loss accumulators ----------------
__global__ void k_init() {
    long i = (long)blockIdx.x * blockDim.x + threadIdx.x;
    long stride = (long)gridDim.x * blockDim.x;
    for (long p = i; p < (long)BATCH * HID; p += stride) {
        g_hA[p] = 0.f;
        g_c[p]  = 0.f;
    }
    if (i < T_SEQ) { g_num[i] = 0.f; g_den[i] = 0.f; }
}

// ---------------- w_sum[j] = sum_k W_decay[j,k] ----------------
__global__ void k_wsum(const float* __restrict__ Wd) {
    int row = blockIdx.x;
    __shared__ float red[256];
    float s = 0.f;
    for (int k = threadIdx.x; k < NF; k += 256)
        s += Wd[(size_t)row * NF + k];
    red[threadIdx.x] = s;
    __syncthreads();
    for (int off = 128; off; off >>= 1) {
        if (threadIdx.x < off) red[threadIdx.x] += red[threadIdx.x + off];
        __syncthreads();
    }
    if (threadIdx.x == 0) g_wsum[row] = red[0];
}

// ---------------- big parallel GEMM: G0 = values @ W_ih[:, :812].T + b_ih + b_hh
// M=163840 (r = b*20+t), N=1600, K=812. Tiles: 128x64x16, 256 threads, 8x4/thread.
__global__ __launch_bounds__(256) void k_gemm_in(
    const float* __restrict__ V, const float* __restrict__ Wih,
    const float* __restrict__ bih, const float* __restrict__ bhh)
{
    __shared__ float As[16][128];
    __shared__ float Bs[16][64];
    int tid = threadIdx.x;
    int bm = blockIdx.x, bn = blockIdx.y;

    int aRow = tid >> 1, aK0 = (tid & 1) * 8;   // 128 rows x 16 k, 8 elems/thread
    int bRow = tid >> 2, bK0 = (tid & 3) * 4;   // 64 rows  x 16 k, 4 elems/thread
    const float* Aptr = V   + (size_t)(bm * 128 + aRow) * NF;
    const float* Bptr = Wih + (size_t)(bn * 64  + bRow) * (NF + 1);

    int ty = tid >> 4, tx = tid & 15;
    float acc[8][4];
    #pragma unroll
    for (int i = 0; i < 8; i++)
        #pragma unroll
        for (int j = 0; j < 4; j++) acc[i][j] = 0.f;

    for (int kt = 0; kt < NF; kt += 16) {
        #pragma unroll
        for (int u = 0; u < 8; u++) {
            int k = kt + aK0 + u;
            As[aK0 + u][aRow] = (k < NF) ? Aptr[k] : 0.f;
        }
        #pragma unroll
        for (int u = 0; u < 4; u++) {
            int k = kt + bK0 + u;
            Bs[bK0 + u][bRow] = (k < NF) ? Bptr[k] : 0.f;
        }
        __syncthreads();
        #pragma unroll
        for (int kk = 0; kk < 16; kk++) {
            float a[8], b[4];
            #pragma unroll
            for (int i = 0; i < 8; i++) a[i] = As[kk][ty * 8 + i];
            #pragma unroll
            for (int j = 0; j < 4; j++) b[j] = Bs[kk][tx * 4 + j];
            #pragma unroll
            for (int i = 0; i < 8; i++)
                #pragma unroll
                for (int j = 0; j < 4; j++)
                    acc[i][j] = fmaf(a[i], b[j], acc[i][j]);
        }
        __syncthreads();
    }

    int ncol = bn * 64 + tx * 4;
    float bias[4];
    #pragma unroll
    for (int j = 0; j < 4; j++) bias[j] = bih[ncol + j] + bhh[ncol + j];
    #pragma unroll
    for (int i = 0; i < 8; i++) {
        size_t r = (size_t)bm * 128 + ty * 8 + i;
        float4 st;
        st.x = acc[i][0] + bias[0];
        st.y = acc[i][1] + bias[1];
        st.z = acc[i][2] + bias[2];
        st.w = acc[i][3] + bias[3];
        *(float4*)&g_G0[r * NG + ncol] = st;
    }
}

// ---------------- per-step: decay h, regression x_h, imputation, loss terms ----
__global__ void k_pre(const float* __restrict__ V, const float* __restrict__ masks,
                      const float* __restrict__ deltas, const float* __restrict__ bdec,
                      const float* __restrict__ Wreg, const float* __restrict__ breg,
                      float* __restrict__ outImp, int t, int cur)
{
    int b = blockIdx.x, tid = threadIdx.x;
    float* h = cur ? g_hB : g_hA;
    float d = deltas[b * T_SEQ + t];
    float m = masks[b * T_SEQ + t];
    float s = 0.f;
    for (int j = tid; j < HID; j += 128) {
        float w = fmaf(d, g_wsum[j], bdec[j]);
        float gamma = expf(-fmaxf(w, 0.f));
        float hv = h[(size_t)b * HID + j] * gamma;
        h[(size_t)b * HID + j] = hv;
        s = fmaf(hv, Wreg[j], s);
    }
    __shared__ float red[128];
    red[tid] = s;
    __syncthreads();
    for (int off = 64; off; off >>= 1) {
        if (tid < off) red[tid] += red[tid + off];
        __syncthreads();
    }
    if (tid == 0) {
        float xh = red[0] + breg[0];
        float v  = V[((size_t)b * T_SEQ + t) * NF + (NF - 1)]; // VAR = 811
        float xvar = v * m + (1.f - m) * xh;
        outImp[b * T_SEQ + t] = xvar;
        g_alpha[b] = xvar - v;
        atomicAdd(&g_num[t], fabsf(xvar - xh) * m);
        atomicAdd(&g_den[t], m);
    }
}

// ---------------- recurrent GEMM + fused LSTM cell ----------------
// gates[b, g*400+j] = G0 + alpha*Wih[:,811] + m*Wih[:,812] + h @ W_hh.T
// Block: 128 b-rows x 16 j-cols x 4 gates. K=400 in tiles of 16. 256 threads.
__global__ __launch_bounds__(256) void k_gates(
    const float* __restrict__ Whh, const float* __restrict__ Wih,
    const float* __restrict__ masks, int t, int cur)
{
    const float* hsrc = cur ? g_hB : g_hA;
    float*       hdst = cur ? g_hA : g_hB;

    __shared__ float As[16][128];
    __shared__ float Bs[16][64];
    __shared__ float wvs[64], wms[64];

    int tid = threadIdx.x;
    int bm = blockIdx.x, bj = blockIdx.y;

    if (tid < 64) {
        int g = tid >> 4, jl = tid & 15;
        size_t grow = (size_t)(g * HID + bj * 16 + jl) * (NF + 1);
        wvs[tid] = Wih[grow + (NF - 1)]; // column 811 (VAR)
        wms[tid] = Wih[grow + NF];       // column 812 (mask)
    }

    int aRow = tid >> 1, aK0 = (tid & 1) * 8;
    int bRow = tid >> 2, bK0 = (tid & 3) * 4;
    const float* Aptr = hsrc + (size_t)(bm * 128 + aRow) * HID;
    int growi = (bRow >> 4) * HID + bj * 16 + (bRow & 15);
    const float* Bptr = Whh + (size_t)growi * HID;

    int ty = tid >> 4, tx = tid & 15;
    float acc[8][4];
    #pragma unroll
    for (int i = 0; i < 8; i++)
        #pragma unroll
        for (int g = 0; g < 4; g++) acc[i][g] = 0.f;

    for (int kt = 0; kt < HID; kt += 16) {
        #pragma unroll
        for (int u = 0; u < 8; u++) As[aK0 + u][aRow] = Aptr[kt + aK0 + u];
        #pragma unroll
        for (int u = 0; u < 4; u++) Bs[bK0 + u][bRow] = Bptr[kt + bK0 + u];
        __syncthreads();
        #pragma unroll
        for (int kk = 0; kk < 16; kk++) {
            float a[8], bb[4];
            #pragma unroll
            for (int i = 0; i < 8; i++) a[i] = As[kk][ty * 8 + i];
            #pragma unroll
            for (int g = 0; g < 4; g++) bb[g] = Bs[kk][g * 16 + tx];
            #pragma unroll
            for (int i = 0; i < 8; i++)
                #pragma unroll
                for (int g = 0; g < 4; g++)
                    acc[i][g] = fmaf(a[i], bb[g], acc[i][g]);
        }
        __syncthreads();
    }

    int jg = bj * 16 + tx;
    #pragma unroll
    for (int i = 0; i < 8; i++) {
        int b = bm * 128 + ty * 8 + i;
        size_t g0 = ((size_t)b * T_SEQ + t) * NG;
        float alpha = g_alpha[b];
        float m = masks[b * T_SEQ + t];
        float ig = acc[i][0] + g_G0[g0 + jg]           + alpha * wvs[tx]      + m * wms[tx];
        float fg = acc[i][1] + g_G0[g0 + HID + jg]     + alpha * wvs[16 + tx] + m * wms[16 + tx];
        float gg = acc[i][2] + g_G0[g0 + 2 * HID + jg] + alpha * wvs[32 + tx] + m * wms[32 + tx];
        float og = acc[i][3] + g_G0[g0 + 3 * HID + jg] + alpha * wvs[48 + tx] + m * wms[48 + tx];
        float si = 1.f / (1.f + expf(-ig));
        float sf = 1.f / (1.f + expf(-fg));
        float so = 1.f / (1.f + expf(-og));
        float tg = tanhf(gg);
        size_t ci = (size_t)b * HID + jg;
        float c = sf * g_c[ci] + si * tg;
        g_c[ci] = c;
        hdst[ci] = so * tanhf(c);
    }
}

// ---------------- finalize loss ----------------
__global__ void k_final(float* __restrict__ out) {
    if (threadIdx.x == 0) {
        float s = 0.f;
        for (int t = 0; t < T_SEQ; t++) s += g_num[t] / (g_den[t] + 1e-5f);
        out[0] = s / (float)T_SEQ;
    }
}

extern "C" void kernel_launch(void* const* d_in, const int* in_sizes, int n_in,
                              void* d_out, int out_size)
{
    const float* V      = (const float*)d_in[0];
    const float* masks  = (const float*)d_in[1];
    const float* deltas = (const float*)d_in[2];
    const float* Wdec   = (const float*)d_in[3];
    const float* bdec   = (const float*)d_in[4];
    const float* Wreg   = (const float*)d_in[5];
    const float* breg   = (const float*)d_in[6];
    const float* Wih    = (const float*)d_in[7];
    const float* Whh    = (const float*)d_in[8];
    const float* bih    = (const float*)d_in[9];
    const float* bhh    = (const float*)d_in[10];
    float* out = (float*)d_out;

    k_init<<<1024, 256>>>();
    k_wsum<<<HID, 256>>>(Wdec);

    dim3 g2(MROWS / 128, NG / 64);
    k_gemm_in<<<g2, 256>>>(V, Wih, bih, bhh);

    for (int t = 0; t < T_SEQ; t++) {
        int cur = t & 1;
        k_pre<<<BATCH, 128>>>(V, masks, deltas, bdec, Wreg, breg, out + 1, t, cur);
        dim3 g4(BATCH / 128, HID / 16);
        k_gates<<<g4, 256>>>(Whh, Wih, masks, t, cur);
    }
    k_final<<<1, 32>>>(out);
}

// round 3
// speedup vs baseline: 2.3926x; 2.3926x over previous
#include <cuda_runtime.h>
#include <cuda_bf16.h>
#include <math.h>
#include <stdint.h>

#define T_SEQ 20
#define NF    812
#define HID   400
#define NG    1600            // 4*HID
#define BATCH 8192
#define MROWS (BATCH * T_SEQ) // 163840
#define KP    832             // padded per-section K for big GEMM (26*32)
#define K2    (3 * KP)        // 2496 bf16-split K (78 * 32)
#define KH2   1216            // split K for recurrent GEMM: 3*400=1200 -> pad 1216 (38*32)
#define NCBIG (K2 / 32)       // 78
#define NCGAT (KH2 / 32)      // 38

// ---------------- device scratch ----------------
__device__ __nv_bfloat16 g_V2[(size_t)MROWS * K2];    // ~818 MB  split values
__device__ __nv_bfloat16 g_W2[(size_t)NG * K2];       // ~8 MB    split W_ih (perm rows)
__device__ __nv_bfloat16 g_Wh2[(size_t)NG * KH2];     // ~3.9 MB  split W_hh (perm rows)
__device__ __nv_bfloat16 g_h2[(size_t)BATCH * KH2];   // ~19.9 MB split decayed h
__device__ float g_G0[(size_t)MROWS * NG];            // ~1.05 GB perm gate pre-acts
__device__ float g_h [BATCH * HID];
__device__ float g_c [BATCH * HID];
__device__ float g_alpha[BATCH];
__device__ float g_wsum[HID];
__device__ float g_num[T_SEQ];
__device__ float g_den[T_SEQ];

// ---------------- PTX helpers ----------------
__device__ __forceinline__ uint32_t smem_u32(const void* p) {
    uint32_t a;
    asm("{ .reg .u64 t; cvta.to.shared.u64 t, %1; cvt.u32.u64 %0, t; }" : "=r"(a) : "l"(p));
    return a;
}
__device__ __forceinline__ void cp_async16(uint32_t saddr, const void* gaddr) {
    asm volatile("cp.async.cg.shared.global [%0], [%1], 16;\n" :: "r"(saddr), "l"(gaddr) : "memory");
}
__device__ __forceinline__ void ldsm_x4(uint32_t* r, uint32_t addr) {
    asm volatile("ldmatrix.sync.aligned.m8n8.x4.shared.b16 {%0,%1,%2,%3}, [%4];"
                 : "=r"(r[0]), "=r"(r[1]), "=r"(r[2]), "=r"(r[3]) : "r"(addr));
}
__device__ __forceinline__ void mma16816(float* d, const uint32_t* a, const uint32_t* b) {
    asm volatile(
        "mma.sync.aligned.m16n8k16.row.col.f32.bf16.bf16.f32 "
        "{%0,%1,%2,%3}, {%4,%5,%6,%7}, {%8,%9}, {%0,%1,%2,%3};"
        : "+f"(d[0]), "+f"(d[1]), "+f"(d[2]), "+f"(d[3])
        : "r"(a[0]), "r"(a[1]), "r"(a[2]), "r"(a[3]), "r"(b[0]), "r"(b[1]));
}

// smem tile geometry: A 128 rows x 32 halves (80B stride), B 64 rows x 32 halves (80B stride)
#define A_STRIDE_B 80
#define A_TILE_B   (128 * A_STRIDE_B)  // 10240
#define B_TILE_B   (64 * A_STRIDE_B)   // 5120
#define BUF_B      (A_TILE_B + B_TILE_B) // 15360
#define SMEM_DYN   33792               // max(2*BUF_B=30720, stage 128*66*4=33792)

// ---------------- shared mma mainloop (BM=128, BN=64, BK=32, 8 warps) ----------------
__device__ __forceinline__ void gemm_mainloop(
    const __nv_bfloat16* Abase, const __nv_bfloat16* Bbase,
    int aStride, int bStride, int nChunks,
    uint32_t sbuf, float acc[2][4][4], int tid)
{
    int lane = tid & 31, w = tid >> 5;
    int wm = w & 3, wn = w >> 2;
    uint32_t aOffBase = (uint32_t)((wm * 32 + (lane & 15)) * A_STRIDE_B + ((lane >> 4) << 4));
    uint32_t bOffBase = (uint32_t)(A_TILE_B +
        (wn * 32 + ((lane >> 4) << 3) + (lane & 7)) * A_STRIDE_B + (((lane >> 3) & 1) << 4));

    // preload chunk 0 -> buf 0
    {
        int row = tid >> 2, seg = tid & 3;
        cp_async16(sbuf + row * A_STRIDE_B + seg * 16, Abase + (size_t)row * aStride + seg * 8);
        cp_async16(sbuf + (row + 64) * A_STRIDE_B + seg * 16, Abase + (size_t)(row + 64) * aStride + seg * 8);
        cp_async16(sbuf + A_TILE_B + row * A_STRIDE_B + seg * 16, Bbase + (size_t)row * bStride + seg * 8);
        asm volatile("cp.async.commit_group;\n" ::: "memory");
    }

    for (int c = 0; c < nChunks; c++) {
        if (c + 1 < nChunks) {
            uint32_t dst = sbuf + ((c + 1) & 1) * BUF_B;
            int koff = (c + 1) * 32;
            int row = tid >> 2, seg = tid & 3;
            cp_async16(dst + row * A_STRIDE_B + seg * 16,
                       Abase + (size_t)row * aStride + koff + seg * 8);
            cp_async16(dst + (row + 64) * A_STRIDE_B + seg * 16,
                       Abase + (size_t)(row + 64) * aStride + koff + seg * 8);
            cp_async16(dst + A_TILE_B + row * A_STRIDE_B + seg * 16,
                       Bbase + (size_t)row * bStride + koff + seg * 8);
            asm volatile("cp.async.commit_group;\n" ::: "memory");
            asm volatile("cp.async.wait_group 1;\n" ::: "memory");
        } else {
            asm volatile("cp.async.wait_group 0;\n" ::: "memory");
        }
        __syncthreads();

        uint32_t cur = sbuf + (c & 1) * BUF_B;
        #pragma unroll
        for (int kc = 0; kc < 2; kc++) {
            uint32_t aregs[2][4], bregs[2][4];
            ldsm_x4(aregs[0], cur + aOffBase + kc * 32);
            ldsm_x4(aregs[1], cur + aOffBase + 16 * A_STRIDE_B + kc * 32);
            ldsm_x4(bregs[0], cur + bOffBase + kc * 32);
            ldsm_x4(bregs[1], cur + bOffBase + 16 * A_STRIDE_B + kc * 32);
            #pragma unroll
            for (int mi = 0; mi < 2; mi++)
                #pragma unroll
                for (int ni = 0; ni < 4; ni++)
                    mma16816(acc[mi][ni], aregs[mi], &bregs[ni >> 1][(ni & 1) * 2]);
        }
        __syncthreads();
    }
}

// stage acc -> smem fp32 [128][66]
__device__ __forceinline__ void stage_acc(float* stage, float acc[2][4][4], int tid) {
    int lane = tid & 31, w = tid >> 5;
    int wm = w & 3, wn = w >> 2;
    #pragma unroll
    for (int mi = 0; mi < 2; mi++)
        #pragma unroll
        for (int ni = 0; ni < 4; ni++) {
            int r0 = wm * 32 + mi * 16 + (lane >> 2);
            int cc = wn * 32 + ni * 8 + (lane & 3) * 2;
            *(float2*)&stage[r0 * 66 + cc]       = make_float2(acc[mi][ni][0], acc[mi][ni][1]);
            *(float2*)&stage[(r0 + 8) * 66 + cc] = make_float2(acc[mi][ni][2], acc[mi][ni][3]);
        }
}

// ---------------- init ----------------
__global__ void k_init() {
    long i = (long)blockIdx.x * blockDim.x + threadIdx.x;
    long stride = (long)gridDim.x * blockDim.x;
    for (long p = i; p < (long)BATCH * HID; p += stride) { g_h[p] = 0.f; g_c[p] = 0.f; }
    for (long p = i; p < (long)BATCH * KH2; p += stride) g_h2[p] = __float2bfloat16(0.f);
    if (i < T_SEQ) { g_num[i] = 0.f; g_den[i] = 0.f; }
}

// ---------------- w_sum ----------------
__global__ void k_wsum(const float* __restrict__ Wd) {
    int row = blockIdx.x;
    __shared__ float red[256];
    float s = 0.f;
    for (int k = threadIdx.x; k < NF; k += 256) s += Wd[(size_t)row * NF + k];
    red[threadIdx.x] = s;
    __syncthreads();
    for (int off = 128; off; off >>= 1) {
        if (threadIdx.x < off) red[threadIdx.x] += red[threadIdx.x + off];
        __syncthreads();
    }
    if (threadIdx.x == 0) g_wsum[row] = red[0];
}

// ---------------- V2 = [hi(V), hi(V), lo(V)] ----------------
__global__ void k_convV(const float* __restrict__ V) {
    int r = blockIdx.x;
    const float* src = V + (size_t)r * NF;
    __nv_bfloat16* dst = g_V2 + (size_t)r * K2;
    for (int k = threadIdx.x; k < KP; k += 256) {
        float v = (k < NF) ? src[k] : 0.f;
        __nv_bfloat16 hi = __float2bfloat16(v);
        __nv_bfloat16 lo = __float2bfloat16(v - __bfloat162float(hi));
        dst[k] = hi; dst[KP + k] = hi; dst[2 * KP + k] = lo;
    }
}

// ---------------- W2 rows permuted (n = j*4+g), [hi, lo, hi] ----------------
__global__ void k_convW(const float* __restrict__ Wih) {
    int n = blockIdx.x;                       // perm index 0..1599
    int orig = (n & 3) * HID + (n >> 2);      // g*400 + j
    __nv_bfloat16* dst = g_W2 + (size_t)n * K2;
    const float* src = Wih + (size_t)orig * (NF + 1);
    for (int k = threadIdx.x; k < KP; k += 256) {
        float w = (k < NF) ? src[k] : 0.f;
        __nv_bfloat16 hi = __float2bfloat16(w);
        __nv_bfloat16 lo = __float2bfloat16(w - __bfloat162float(hi));
        dst[k] = hi; dst[KP + k] = lo; dst[2 * KP + k] = hi;
    }
}

// ---------------- Wh2 rows permuted, [hi, lo, hi], K padded to 1216 ----------------
__global__ void k_convWh(const float* __restrict__ Whh) {
    int n = blockIdx.x;
    int orig = (n & 3) * HID + (n >> 2);
    __nv_bfloat16* dst = g_Wh2 + (size_t)n * KH2;
    const float* src = Whh + (size_t)orig * HID;
    for (int k = threadIdx.x; k < HID; k += 256) {
        float w = src[k];
        __nv_bfloat16 hi = __float2bfloat16(w);
        __nv_bfloat16 lo = __float2bfloat16(w - __bfloat162float(hi));
        dst[k] = hi; dst[HID + k] = lo; dst[2 * HID + k] = hi;
    }
    if (threadIdx.x < KH2 - 3 * HID) dst[3 * HID + threadIdx.x] = __float2bfloat16(0.f);
}

// ---------------- big GEMM: G0(perm) = V2 @ W2^T + bias ----------------
__global__ __launch_bounds__(256) void k_bigmma(const float* __restrict__ bih,
                                                const float* __restrict__ bhh)
{
    extern __shared__ char smem[];
    uint32_t sbuf = smem_u32(smem);
    float* stage = (float*)smem;
    __shared__ float biasS[64];
    int tid = threadIdx.x;
    int bn = blockIdx.x, bm = blockIdx.y;

    if (tid < 64) {
        int np = bn * 64 + tid;
        int orig = (np & 3) * HID + (np >> 2);
        biasS[tid] = bih[orig] + bhh[orig];
    }

    float acc[2][4][4];
    #pragma unroll
    for (int a = 0; a < 2; a++)
        #pragma unroll
        for (int b = 0; b < 4; b++)
            #pragma unroll
            for (int c = 0; c < 4; c++) acc[a][b][c] = 0.f;

    gemm_mainloop(g_V2 + (size_t)(bm * 128) * K2, g_W2 + (size_t)(bn * 64) * K2,
                  K2, K2, NCBIG, sbuf, acc, tid);

    stage_acc(stage, acc, tid);
    __syncthreads();

    #pragma unroll
    for (int i = 0; i < 8; i++) {
        int lin = tid + i * 256;      // 0..2047 float4 units
        int r = lin >> 4, c4 = lin & 15;
        float4 v;
        v.x = stage[r * 66 + c4 * 4 + 0] + biasS[c4 * 4 + 0];
        v.y = stage[r * 66 + c4 * 4 + 1] + biasS[c4 * 4 + 1];
        v.z = stage[r * 66 + c4 * 4 + 2] + biasS[c4 * 4 + 2];
        v.w = stage[r * 66 + c4 * 4 + 3] + biasS[c4 * 4 + 3];
        *(float4*)&g_G0[(size_t)(bm * 128 + r) * NG + bn * 64 + c4 * 4] = v;
    }
}

// ---------------- per-step: decay h -> split bf16, regression, loss ----------
__global__ void k_pre(const float* __restrict__ V, const float* __restrict__ masks,
                      const float* __restrict__ deltas, const float* __restrict__ bdec,
                      const float* __restrict__ Wreg, const float* __restrict__ breg,
                      float* __restrict__ outImp, int t)
{
    int b = blockIdx.x, tid = threadIdx.x;
    float d = deltas[b * T_SEQ + t];
    float m = masks[b * T_SEQ + t];
    __nv_bfloat16* h2 = g_h2 + (size_t)b * KH2;
    float s = 0.f;
    for (int j = tid; j < HID; j += 128) {
        float w = fmaf(d, g_wsum[j], bdec[j]);
        float gamma = expf(-fmaxf(w, 0.f));
        float hv = g_h[(size_t)b * HID + j] * gamma;
        __nv_bfloat16 hi = __float2bfloat16(hv);
        __nv_bfloat16 lo = __float2bfloat16(hv - __bfloat162float(hi));
        h2[j] = hi; h2[HID + j] = hi; h2[2 * HID + j] = lo;
        s = fmaf(hv, Wreg[j], s);
    }
    __shared__ float red[128];
    red[tid] = s;
    __syncthreads();
    for (int off = 64; off; off >>= 1) {
        if (tid < off) red[tid] += red[tid + off];
        __syncthreads();
    }
    if (tid == 0) {
        float xh = red[0] + breg[0];
        float v  = V[((size_t)b * T_SEQ + t) * NF + (NF - 1)];
        float xvar = v * m + (1.f - m) * xh;
        outImp[b * T_SEQ + t] = xvar;
        g_alpha[b] = xvar - v;
        atomicAdd(&g_num[t], fabsf(xvar - xh) * m);
        atomicAdd(&g_den[t], m);
    }
}

// ---------------- recurrent GEMM + fused LSTM cell (mma.sync) ----------------
__global__ __launch_bounds__(256) void k_gates(
    const float* __restrict__ Wih, const float* __restrict__ masks, int t)
{
    extern __shared__ char smem[];
    uint32_t sbuf = smem_u32(smem);
    float* stage = (float*)smem;
    __shared__ float wvS[64], wmS[64];
    int tid = threadIdx.x;
    int bn = blockIdx.x, bm = blockIdx.y;

    if (tid < 64) {
        int np = bn * 64 + tid;
        int orig = (np & 3) * HID + (np >> 2);
        wvS[tid] = Wih[(size_t)orig * (NF + 1) + (NF - 1)];
        wmS[tid] = Wih[(size_t)orig * (NF + 1) + NF];
    }

    float acc[2][4][4];
    #pragma unroll
    for (int a = 0; a < 2; a++)
        #pragma unroll
        for (int b = 0; b < 4; b++)
            #pragma unroll
            for (int c = 0; c < 4; c++) acc[a][b][c] = 0.f;

    gemm_mainloop(g_h2 + (size_t)(bm * 128) * KH2, g_Wh2 + (size_t)(bn * 64) * KH2,
                  KH2, KH2, NCGAT, sbuf, acc, tid);

    stage_acc(stage, acc, tid);
    __syncthreads();

    #pragma unroll
    for (int i = 0; i < 8; i++) {
        int lin = tid + i * 256;       // 0..2047 = 128 rows x 16 j
        int r = lin >> 4, jl = lin & 15;
        int b = bm * 128 + r;
        float alpha = g_alpha[b];
        float m = masks[b * T_SEQ + t];
        int c0 = jl * 4;
        float4 g0 = *(const float4*)&g_G0[((size_t)b * T_SEQ + t) * NG + bn * 64 + c0];
        float ig = stage[r * 66 + c0 + 0] + g0.x + alpha * wvS[c0 + 0] + m * wmS[c0 + 0];
        float fg = stage[r * 66 + c0 + 1] + g0.y + alpha * wvS[c0 + 1] + m * wmS[c0 + 1];
        float gg = stage[r * 66 + c0 + 2] + g0.z + alpha * wvS[c0 + 2] + m * wmS[c0 + 2];
        float og = stage[r * 66 + c0 + 3] + g0.w + alpha * wvS[c0 + 3] + m * wmS[c0 + 3];
        float si = 1.f / (1.f + expf(-ig));
        float sf = 1.f / (1.f + expf(-fg));
        float so = 1.f / (1.f + expf(-og));
        float tg = tanhf(gg);
        int j = bn * 16 + jl;
        size_t ci = (size_t)b * HID + j;
        float c = sf * g_c[ci] + si * tg;
        g_c[ci] = c;
        g_h[ci] = so * tanhf(c);
    }
}

// ---------------- finalize loss ----------------
__global__ void k_final(float* __restrict__ out) {
    if (threadIdx.x == 0) {
        float s = 0.f;
        for (int tt = 0; tt < T_SEQ; tt++) s += g_num[tt] / (g_den[tt] + 1e-5f);
        out[0] = s / (float)T_SEQ;
    }
}

extern "C" void kernel_launch(void* const* d_in, const int* in_sizes, int n_in,
                              void* d_out, int out_size)
{
    const float* V      = (const float*)d_in[0];
    const float* masks  = (const float*)d_in[1];
    const float* deltas = (const float*)d_in[2];
    const float* Wdec   = (const float*)d_in[3];
    const float* bdec   = (const float*)d_in[4];
    const float* Wreg   = (const float*)d_in[5];
    const float* breg   = (const float*)d_in[6];
    const float* Wih    = (const float*)d_in[7];
    const float* Whh    = (const float*)d_in[8];
    const float* bih    = (const float*)d_in[9];
    const float* bhh    = (const float*)d_in[10];
    float* out = (float*)d_out;

    k_init<<<1024, 256>>>();
    k_wsum<<<HID, 256>>>(Wdec);

    k_convV<<<MROWS, 256>>>(V);
    k_convW<<<NG, 256>>>(Wih);
    k_convWh<<<NG, 256>>>(Whh);

    dim3 gB(NG / 64, MROWS / 128);   // (25, 1280); bn fastest -> A tile L2 reuse
    k_bigmma<<<gB, 256, SMEM_DYN>>>(bih, bhh);

    for (int t = 0; t < T_SEQ; t++) {
        k_pre<<<BATCH, 128>>>(V, masks, deltas, bdec, Wreg, breg, out + 1, t);
        dim3 g4(NG / 64, BATCH / 128); // (25, 64)
        k_gates<<<g4, 256, SMEM_DYN>>>(Wih, masks, t);
    }
    k_final<<<1, 32>>>(out);
}

// round 4
// speedup vs baseline: 3.2387x; 1.3537x over previous
#include <cuda_runtime.h>
#include <cuda_fp16.h>
#include <math.h>
#include <stdint.h>

#define T_SEQ 20
#define NF    812
#define HID   400
#define NG    1600            // 4*HID
#define BATCH 8192
#define MROWS (BATCH * T_SEQ) // 163840
#define KP    832             // padded per-section K for big GEMM (26*32)
#define K2    (2 * KP)        // 1664: fp16 2-term split [hi, lo]
#define KH2   832             // gates K: [hi(400), lo(400), pad(32)]
#define NCBIG (K2 / 32)       // 52
#define NCGAT (KH2 / 32)      // 26

// ---------------- device scratch ----------------
__device__ __half g_V2[(size_t)MROWS * K2];          // ~545 MB  split values
__device__ __half g_W2[(size_t)NG * K2];             // ~5.3 MB  W_ih hi duplicated (perm rows)
__device__ __half g_Wh2[(size_t)NG * KH2];           // ~2.7 MB  W_hh hi duplicated (perm rows)
__device__ __half g_h2[2][(size_t)BATCH * KH2];      // 2x 13.6 MB split decayed h (dbl buf)
__device__ float g_G0[(size_t)MROWS * NG];           // ~1.05 GB perm gate pre-acts
__device__ float g_c [BATCH * HID];
__device__ float g_alpha[BATCH];
__device__ float g_xh[2][BATCH];
__device__ float g_wsum[HID];
__device__ float g_num[T_SEQ];
__device__ float g_den[T_SEQ];

// ---------------- PTX helpers ----------------
__device__ __forceinline__ uint32_t smem_u32(const void* p) {
    uint32_t a;
    asm("{ .reg .u64 t; cvta.to.shared.u64 t, %1; cvt.u32.u64 %0, t; }" : "=r"(a) : "l"(p));
    return a;
}
__device__ __forceinline__ void cp_async16(uint32_t saddr, const void* gaddr) {
    asm volatile("cp.async.cg.shared.global [%0], [%1], 16;\n" :: "r"(saddr), "l"(gaddr) : "memory");
}
__device__ __forceinline__ void ldsm_x4(uint32_t* r, uint32_t addr) {
    asm volatile("ldmatrix.sync.aligned.m8n8.x4.shared.b16 {%0,%1,%2,%3}, [%4];"
                 : "=r"(r[0]), "=r"(r[1]), "=r"(r[2]), "=r"(r[3]) : "r"(addr));
}
__device__ __forceinline__ void mma16816(float* d, const uint32_t* a, const uint32_t* b) {
    asm volatile(
        "mma.sync.aligned.m16n8k16.row.col.f32.f16.f16.f32 "
        "{%0,%1,%2,%3}, {%4,%5,%6,%7}, {%8,%9}, {%0,%1,%2,%3};"
        : "+f"(d[0]), "+f"(d[1]), "+f"(d[2]), "+f"(d[3])
        : "r"(a[0]), "r"(a[1]), "r"(a[2]), "r"(a[3]), "r"(b[0]), "r"(b[1]));
}

// smem tile geometry: A 128 rows x 32 halves (80B stride), B 64 rows x 32 halves
#define A_STRIDE_B 80
#define A_TILE_B   (128 * A_STRIDE_B)    // 10240
#define B_TILE_B   (64 * A_STRIDE_B)     // 5120
#define BUF_B      (A_TILE_B + B_TILE_B) // 15360
#define SMEM_DYN   33792                 // max(2*BUF_B=30720, stage 128*66*4=33792)

// ---------------- shared mma mainloop (BM=128, BN=64, BK=32, 8 warps) ----------------
__device__ __forceinline__ void gemm_mainloop(
    const __half* Abase, const __half* Bbase,
    int aStride, int bStride, int nChunks,
    uint32_t sbuf, float acc[2][4][4], int tid)
{
    int lane = tid & 31, w = tid >> 5;
    int wm = w & 3, wn = w >> 2;
    uint32_t aOffBase = (uint32_t)((wm * 32 + (lane & 15)) * A_STRIDE_B + ((lane >> 4) << 4));
    uint32_t bOffBase = (uint32_t)(A_TILE_B +
        (wn * 32 + ((lane >> 4) << 3) + (lane & 7)) * A_STRIDE_B + (((lane >> 3) & 1) << 4));

    {
        int row = tid >> 2, seg = tid & 3;
        cp_async16(sbuf + row * A_STRIDE_B + seg * 16, Abase + (size_t)row * aStride + seg * 8);
        cp_async16(sbuf + (row + 64) * A_STRIDE_B + seg * 16, Abase + (size_t)(row + 64) * aStride + seg * 8);
        cp_async16(sbuf + A_TILE_B + row * A_STRIDE_B + seg * 16, Bbase + (size_t)row * bStride + seg * 8);
        asm volatile("cp.async.commit_group;\n" ::: "memory");
    }

    for (int c = 0; c < nChunks; c++) {
        if (c + 1 < nChunks) {
            uint32_t dst = sbuf + ((c + 1) & 1) * BUF_B;
            int koff = (c + 1) * 32;
            int row = tid >> 2, seg = tid & 3;
            cp_async16(dst + row * A_STRIDE_B + seg * 16,
                       Abase + (size_t)row * aStride + koff + seg * 8);
            cp_async16(dst + (row + 64) * A_STRIDE_B + seg * 16,
                       Abase + (size_t)(row + 64) * aStride + koff + seg * 8);
            cp_async16(dst + A_TILE_B + row * A_STRIDE_B + seg * 16,
                       Bbase + (size_t)row * bStride + koff + seg * 8);
            asm volatile("cp.async.commit_group;\n" ::: "memory");
            asm volatile("cp.async.wait_group 1;\n" ::: "memory");
        } else {
            asm volatile("cp.async.wait_group 0;\n" ::: "memory");
        }
        __syncthreads();

        uint32_t cur = sbuf + (c & 1) * BUF_B;
        #pragma unroll
        for (int kc = 0; kc < 2; kc++) {
            uint32_t aregs[2][4], bregs[2][4];
            ldsm_x4(aregs[0], cur + aOffBase + kc * 32);
            ldsm_x4(aregs[1], cur + aOffBase + 16 * A_STRIDE_B + kc * 32);
            ldsm_x4(bregs[0], cur + bOffBase + kc * 32);
            ldsm_x4(bregs[1], cur + bOffBase + 16 * A_STRIDE_B + kc * 32);
            #pragma unroll
            for (int mi = 0; mi < 2; mi++)
                #pragma unroll
                for (int ni = 0; ni < 4; ni++)
                    mma16816(acc[mi][ni], aregs[mi], &bregs[ni >> 1][(ni & 1) * 2]);
        }
        __syncthreads();
    }
}

// stage acc -> smem fp32 [128][66]
__device__ __forceinline__ void stage_acc(float* stage, float acc[2][4][4], int tid) {
    int lane = tid & 31, w = tid >> 5;
    int wm = w & 3, wn = w >> 2;
    #pragma unroll
    for (int mi = 0; mi < 2; mi++)
        #pragma unroll
        for (int ni = 0; ni < 4; ni++) {
            int r0 = wm * 32 + mi * 16 + (lane >> 2);
            int cc = wn * 32 + ni * 8 + (lane & 3) * 2;
            *(float2*)&stage[r0 * 66 + cc]       = make_float2(acc[mi][ni][0], acc[mi][ni][1]);
            *(float2*)&stage[(r0 + 8) * 66 + cc] = make_float2(acc[mi][ni][2], acc[mi][ni][3]);
        }
}

// ---------------- init ----------------
__global__ void k_init() {
    long i = (long)blockIdx.x * blockDim.x + threadIdx.x;
    long stride = (long)gridDim.x * blockDim.x;
    for (long p = i; p < (long)BATCH * HID; p += stride) g_c[p] = 0.f;
    for (long p = i; p < 2L * BATCH * KH2; p += stride) ((__half*)g_h2)[p] = __float2half(0.f);
    for (long p = i; p < 2L * BATCH; p += stride) ((float*)g_xh)[p] = 0.f;
    if (i < T_SEQ) { g_num[i] = 0.f; g_den[i] = 0.f; }
}

// ---------------- w_sum ----------------
__global__ void k_wsum(const float* __restrict__ Wd) {
    int row = blockIdx.x;
    __shared__ float red[256];
    float s = 0.f;
    for (int k = threadIdx.x; k < NF; k += 256) s += Wd[(size_t)row * NF + k];
    red[threadIdx.x] = s;
    __syncthreads();
    for (int off = 128; off; off >>= 1) {
        if (threadIdx.x < off) red[threadIdx.x] += red[threadIdx.x + off];
        __syncthreads();
    }
    if (threadIdx.x == 0) g_wsum[row] = red[0];
}

// ---------------- V2 = [hi(V), lo(V)] fp16 ----------------
__global__ void k_convV(const float* __restrict__ V) {
    int r = blockIdx.x;
    const float* src = V + (size_t)r * NF;
    __half* dst = g_V2 + (size_t)r * K2;
    for (int k = threadIdx.x; k < KP; k += 256) {
        float v = (k < NF) ? src[k] : 0.f;
        __half hi = __float2half_rn(v);
        __half lo = __float2half_rn(v - __half2float(hi));
        dst[k] = hi; dst[KP + k] = lo;
    }
}

// ---------------- W2 rows permuted (n = j*4+g), [hi, hi] ----------------
__global__ void k_convW(const float* __restrict__ Wih) {
    int n = blockIdx.x;
    int orig = (n & 3) * HID + (n >> 2);
    __half* dst = g_W2 + (size_t)n * K2;
    const float* src = Wih + (size_t)orig * (NF + 1);
    for (int k = threadIdx.x; k < KP; k += 256) {
        float w = (k < NF) ? src[k] : 0.f;
        __half hi = __float2half_rn(w);
        dst[k] = hi; dst[KP + k] = hi;
    }
}

// ---------------- Wh2 rows permuted, [hi(400), hi(400), pad 0] ----------------
__global__ void k_convWh(const float* __restrict__ Whh) {
    int n = blockIdx.x;
    int orig = (n & 3) * HID + (n >> 2);
    __half* dst = g_Wh2 + (size_t)n * KH2;
    const float* src = Whh + (size_t)orig * HID;
    for (int k = threadIdx.x; k < HID; k += 256) {
        __half hi = __float2half_rn(src[k]);
        dst[k] = hi; dst[HID + k] = hi;
    }
    if (threadIdx.x < KH2 - 2 * HID) dst[2 * HID + threadIdx.x] = __float2half(0.f);
}

// ---------------- big GEMM: G0(perm) = V2 @ W2^T + bias ----------------
__global__ __launch_bounds__(256) void k_bigmma(const float* __restrict__ bih,
                                                const float* __restrict__ bhh)
{
    extern __shared__ char smem[];
    uint32_t sbuf = smem_u32(smem);
    float* stage = (float*)smem;
    __shared__ float biasS[64];
    int tid = threadIdx.x;
    int bn = blockIdx.x, bm = blockIdx.y;

    if (tid < 64) {
        int np = bn * 64 + tid;
        int orig = (np & 3) * HID + (np >> 2);
        biasS[tid] = bih[orig] + bhh[orig];
    }

    float acc[2][4][4];
    #pragma unroll
    for (int a = 0; a < 2; a++)
        #pragma unroll
        for (int b = 0; b < 4; b++)
            #pragma unroll
            for (int c = 0; c < 4; c++) acc[a][b][c] = 0.f;

    gemm_mainloop(g_V2 + (size_t)(bm * 128) * K2, g_W2 + (size_t)(bn * 64) * K2,
                  K2, K2, NCBIG, sbuf, acc, tid);

    stage_acc(stage, acc, tid);
    __syncthreads();

    #pragma unroll
    for (int i = 0; i < 8; i++) {
        int lin = tid + i * 256;
        int r = lin >> 4, c4 = lin & 15;
        float4 v;
        v.x = stage[r * 66 + c4 * 4 + 0] + biasS[c4 * 4 + 0];
        v.y = stage[r * 66 + c4 * 4 + 1] + biasS[c4 * 4 + 1];
        v.z = stage[r * 66 + c4 * 4 + 2] + biasS[c4 * 4 + 2];
        v.w = stage[r * 66 + c4 * 4 + 3] + biasS[c4 * 4 + 3];
        *(float4*)&g_G0[(size_t)(bm * 128 + r) * NG + bn * 64 + c4 * 4] = v;
    }
}

// ---------------- per-step tiny kernel: x_var, alpha, loss ----------------
__global__ void k_alpha(const float* __restrict__ V, const float* __restrict__ masks,
                        const float* __restrict__ breg, float* __restrict__ outImp, int t)
{
    int b = blockIdx.x * 256 + threadIdx.x;
    int par = t & 1;
    float nloc = 0.f, dloc = 0.f;
    if (b < BATCH) {
        float m  = masks[b * T_SEQ + t];
        float xh = g_xh[par][b] + breg[0];
        float v  = V[((size_t)b * T_SEQ + t) * NF + (NF - 1)];
        float xvar = v * m + (1.f - m) * xh;
        outImp[b * T_SEQ + t] = xvar;
        g_alpha[b] = xvar - v;
        g_xh[par][b] = 0.f;
        nloc = fabsf(xvar - xh) * m;
        dloc = m;
    }
    #pragma unroll
    for (int off = 16; off; off >>= 1) {
        nloc += __shfl_xor_sync(0xffffffff, nloc, off);
        dloc += __shfl_xor_sync(0xffffffff, dloc, off);
    }
    if ((threadIdx.x & 31) == 0) {
        atomicAdd(&g_num[t], nloc);
        atomicAdd(&g_den[t], dloc);
    }
}

// ---------------- recurrent GEMM + fused LSTM cell + next-step decay ----------------
__global__ __launch_bounds__(256) void k_gates(
    const float* __restrict__ Wih, const float* __restrict__ masks,
    const float* __restrict__ deltas, const float* __restrict__ bdec,
    const float* __restrict__ Wreg, int t)
{
    extern __shared__ char smem[];
    uint32_t sbuf = smem_u32(smem);
    float* stage = (float*)smem;
    __shared__ float wvS[64], wmS[64];
    __shared__ float wsumS[16], bdecS[16], wregS[16];
    int tid = threadIdx.x;
    int bn = blockIdx.x, bm = blockIdx.y;
    int par = t & 1;

    if (tid < 64) {
        int np = bn * 64 + tid;
        int orig = (np & 3) * HID + (np >> 2);
        wvS[tid] = Wih[(size_t)orig * (NF + 1) + (NF - 1)];
        wmS[tid] = Wih[(size_t)orig * (NF + 1) + NF];
    }
    if (tid < 16) {
        int j = bn * 16 + tid;
        wsumS[tid] = g_wsum[j];
        bdecS[tid] = bdec[j];
        wregS[tid] = Wreg[j];
    }

    float acc[2][4][4];
    #pragma unroll
    for (int a = 0; a < 2; a++)
        #pragma unroll
        for (int b = 0; b < 4; b++)
            #pragma unroll
            for (int c = 0; c < 4; c++) acc[a][b][c] = 0.f;

    gemm_mainloop(g_h2[par] + (size_t)(bm * 128) * KH2, g_Wh2 + (size_t)(bn * 64) * KH2,
                  KH2, KH2, NCGAT, sbuf, acc, tid);

    stage_acc(stage, acc, tid);
    __syncthreads();

    __half* h2n = g_h2[1 - par];
    bool more = (t + 1 < T_SEQ);

    #pragma unroll
    for (int i = 0; i < 8; i++) {
        int lin = tid + i * 256;       // 128 rows x 16 j
        int r = lin >> 4, jl = lin & 15;
        int b = bm * 128 + r;
        float alpha = g_alpha[b];
        float m = masks[b * T_SEQ + t];
        int c0 = jl * 4;
        float4 g0 = *(const float4*)&g_G0[((size_t)b * T_SEQ + t) * NG + bn * 64 + c0];
        float ig = stage[r * 66 + c0 + 0] + g0.x + alpha * wvS[c0 + 0] + m * wmS[c0 + 0];
        float fg = stage[r * 66 + c0 + 1] + g0.y + alpha * wvS[c0 + 1] + m * wmS[c0 + 1];
        float gg = stage[r * 66 + c0 + 2] + g0.z + alpha * wvS[c0 + 2] + m * wmS[c0 + 2];
        float og = stage[r * 66 + c0 + 3] + g0.w + alpha * wvS[c0 + 3] + m * wmS[c0 + 3];
        float si = 1.f / (1.f + expf(-ig));
        float sf = 1.f / (1.f + expf(-fg));
        float so = 1.f / (1.f + expf(-og));
        float tg = tanhf(gg);
        int j = bn * 16 + jl;
        size_t ci = (size_t)b * HID + j;
        float c = sf * g_c[ci] + si * tg;
        g_c[ci] = c;
        float hnew = so * tanhf(c);

        float contrib = 0.f;
        if (more) {
            float dnx = deltas[b * T_SEQ + t + 1];
            float w = fmaf(dnx, wsumS[jl], bdecS[jl]);
            float gamma = expf(-fmaxf(w, 0.f));
            float hv = hnew * gamma;
            __half hi = __float2half_rn(hv);
            __half lo = __float2half_rn(hv - __half2float(hi));
            h2n[(size_t)b * KH2 + j] = hi;
            h2n[(size_t)b * KH2 + HID + j] = lo;
            contrib = hv * wregS[jl];
        }
        // reduce over the 16 lanes sharing this b, then one atomic
        #pragma unroll
        for (int off = 8; off; off >>= 1)
            contrib += __shfl_xor_sync(0xffffffff, contrib, off);
        if (more && (tid & 15) == 0)
            atomicAdd(&g_xh[1 - par][b], contrib);
    }
}

// ---------------- finalize loss ----------------
__global__ void k_final(float* __restrict__ out) {
    if (threadIdx.x == 0) {
        float s = 0.f;
        for (int tt = 0; tt < T_SEQ; tt++) s += g_num[tt] / (g_den[tt] + 1e-5f);
        out[0] = s / (float)T_SEQ;
    }
}

extern "C" void kernel_launch(void* const* d_in, const int* in_sizes, int n_in,
                              void* d_out, int out_size)
{
    const float* V      = (const float*)d_in[0];
    const float* masks  = (const float*)d_in[1];
    const float* deltas = (const float*)d_in[2];
    const float* Wdec   = (const float*)d_in[3];
    const float* bdec   = (const float*)d_in[4];
    const float* Wreg   = (const float*)d_in[5];
    const float* breg   = (const float*)d_in[6];
    const float* Wih    = (const float*)d_in[7];
    const float* Whh    = (const float*)d_in[8];
    const float* bih    = (const float*)d_in[9];
    const float* bhh    = (const float*)d_in[10];
    float* out = (float*)d_out;

    k_init<<<2048, 256>>>();
    k_wsum<<<HID, 256>>>(Wdec);

    k_convV<<<MROWS, 256>>>(V);
    k_convW<<<NG, 256>>>(Wih);
    k_convWh<<<NG, 256>>>(Whh);

    dim3 gB(NG / 64, MROWS / 128);   // (25, 1280); bn fastest -> A tile L2 reuse
    k_bigmma<<<gB, 256, SMEM_DYN>>>(bih, bhh);

    for (int t = 0; t < T_SEQ; t++) {
        k_alpha<<<BATCH / 256, 256>>>(V, masks, breg, out + 1, t);
        dim3 g4(NG / 64, BATCH / 128); // (25, 64)
        k_gates<<<g4, 256, SMEM_DYN>>>(Wih, masks, deltas, bdec, Wreg, t);
    }
    k_final<<<1, 32>>>(out);
}